// round 4
// baseline (speedup 1.0000x reference)
#include <cuda_runtime.h>
#include <cstdint>

// HebbianNet, fused persistent kernel (3 layers, grid barrier between).
// Closed form per layer:
//   z[b,o] = sum_i v[b,i]*W[o,i];  vj = relu(z + bias[o])
//   out    = vj + r*( A*S2[b] + Bc*z + (C*vj + D)*S1[b] )
// A,Bc,C,D folded from cw1/cb1/cw2/cb2; r = RATE/batch_num.
// Shapes: B=8, K=1024 all layers, O = 1024,1024,512.
//
// Layout: 128 blocks x 1024 threads. Block owns 8 output rows/layer.
//   Warp w: rq = w&1 (row quad), q = w>>1 (K-sixteenth, 64 floats).
//   Lane l: row = rq*4 + (l>>3), batch = l&7. ONE scalar accumulator
//   per lane -> no shuffle reduction. V and W both read from smem with
//   broadcast-dedup LDS.128 (padded stride 257 float4 -> conflict-free).
// Weights double-buffered in smem via cp.async (W_{L+1} prefetched
// during layer L compute). ~100KB dynamic smem.

#define B_DIM   8
#define K_DIM   1024
#define RATE_F  0.001f
#define NBLK    128
#define NTHR    1024
#define VSTRIDE 257          // float4 stride per padded row

__device__ __align__(16) float g_act1[B_DIM * K_DIM];
__device__ __align__(16) float g_act2[B_DIM * K_DIM];

__device__ unsigned g_count = 0;
__device__ unsigned g_gen   = 0;

__device__ __forceinline__ void grid_bar()
{
    __syncthreads();
    if (threadIdx.x == 0) {
        __threadfence();
        unsigned g = __ldcv(&g_gen);
        if (atomicAdd(&g_count, 1) == NBLK - 1) {
            atomicExch(&g_count, 0);
            __threadfence();
            atomicAdd(&g_gen, 1);
        } else {
            while (__ldcv(&g_gen) == g) __nanosleep(32);
        }
        __threadfence();
    }
    __syncthreads();
}

__device__ __forceinline__ void cp_async16(const float4* smem_dst, const float4* gsrc)
{
    uint32_t sa = (uint32_t)__cvta_generic_to_shared(smem_dst);
    asm volatile("cp.async.cg.shared.global [%0], [%1], 16;" :: "r"(sa), "l"(gsrc));
}
__device__ __forceinline__ void cp_commit() { asm volatile("cp.async.commit_group;"); }
template<int N> __device__ __forceinline__ void cp_wait()
{ asm volatile("cp.async.wait_group %0;" :: "n"(N)); }

// stage 8x1024 floats (2048 float4) into padded smem rows
__device__ __forceinline__ void stage_tile(float4* dst, const float4* src)
{
#pragma unroll
    for (int x = threadIdx.x; x < 2048; x += NTHR) {
        int r = x >> 8, c = x & 255;
        cp_async16(&dst[r * VSTRIDE + c], &src[x]);
    }
}

__device__ __forceinline__ void layer_body(
    const float4* __restrict__ Vs4, const float4* __restrict__ Ws4,
    float* __restrict__ red, float* __restrict__ S1s, float* __restrict__ S2s,
    const float* __restrict__ bias, float* __restrict__ out, int O,
    float A, float Bc, float C, float D, float rr)
{
    const int tid  = threadIdx.x;
    const int wid  = tid >> 5;
    const int lane = tid & 31;

    // per-batch stats: warp w (0..7) -> batch w
    if (wid < B_DIM) {
        float s1 = 0.f, s2 = 0.f;
#pragma unroll
        for (int m = 0; m < 8; ++m) {
            float4 v = Vs4[wid * VSTRIDE + m * 32 + lane];
            s1 += v.x + v.y + v.z + v.w;
            s2 = fmaf(v.x, v.x, s2); s2 = fmaf(v.y, v.y, s2);
            s2 = fmaf(v.z, v.z, s2); s2 = fmaf(v.w, v.w, s2);
        }
#pragma unroll
        for (int off = 16; off > 0; off >>= 1) {
            s1 += __shfl_xor_sync(0xffffffffu, s1, off);
            s2 += __shfl_xor_sync(0xffffffffu, s2, off);
        }
        if (lane == 0) { S1s[wid] = s1; S2s[wid] = s2; }
    }

    // GEMV: lane owns one (row, batch); warp covers K-sixteenth q
    const int rq  = wid & 1;
    const int q   = wid >> 1;            // 0..15
    const int row = rq * 4 + (lane >> 3);
    const int b   = lane & 7;

    const float4* vp = Vs4 + b   * VSTRIDE + q * 16;
    const float4* wp = Ws4 + row * VSTRIDE + q * 16;

    float acc = 0.f;
#pragma unroll
    for (int i = 0; i < 16; ++i) {
        float4 v = vp[i];
        float4 w = wp[i];
        acc = fmaf(w.x, v.x, acc);
        acc = fmaf(w.y, v.y, acc);
        acc = fmaf(w.z, v.z, acc);
        acc = fmaf(w.w, v.w, acc);
    }
    red[q * 64 + row * 8 + b] = acc;     // consecutive words per warp
    __syncthreads();

    // combine K-sixteenths + epilogue (64 lanes: t = row*8 + batch)
    if (tid < 64) {
        const int r  = tid >> 3;
        const int bb = tid & 7;
        const int o  = blockIdx.x * 8 + r;

        float z = 0.f;
#pragma unroll
        for (int qq = 0; qq < 16; ++qq) z += red[qq * 64 + tid];

        float vj = fmaxf(z + bias[o], 0.f);
        float sh = fmaf(A, S2s[bb], fmaf(Bc, z, (C * vj + D) * S1s[bb]));
        out[(size_t)bb * O + o] = fmaf(rr, sh, vj);
    }
}

__global__ __launch_bounds__(NTHR, 1)
void hebbian_fused_kernel(const float* __restrict__ x,
                          const float* __restrict__ W1, const float* __restrict__ b1,
                          const float* __restrict__ W2, const float* __restrict__ b2,
                          const float* __restrict__ W3, const float* __restrict__ b3,
                          const float* __restrict__ cw1, const float* __restrict__ cb1,
                          const float* __restrict__ cw2, const float* __restrict__ cb2,
                          const int*   __restrict__ bn,
                          float*       __restrict__ outp)
{
    extern __shared__ float4 smem_dyn[];
    float4* Vs4 = smem_dyn;                    // 8*257 float4 = 32896 B
    float4* WsA = Vs4 + 8 * VSTRIDE;           // 32896 B
    float4* WsB = WsA + 8 * VSTRIDE;           // 32896 B
    float*  red = (float*)(WsB + 8 * VSTRIDE); // 1024 floats
    float*  S1s = red + 1024;
    float*  S2s = S1s + 8;

    const int o_base = blockIdx.x * 8;

    // kick off V + W1 (group A) and W2 prefetch (group B)
    stage_tile(Vs4, (const float4*)x);
    stage_tile(WsA, (const float4*)(W1 + (size_t)o_base * K_DIM));
    cp_commit();                                              // A
    stage_tile(WsB, (const float4*)(W2 + (size_t)o_base * K_DIM));
    cp_commit();                                              // B

    // fold 1x1 convs into 4 scalars (overlaps the async loads)
    float A = 0.f, Bc = 0.f, C = 0.f, D = 0.f;
#pragma unroll
    for (int h = 0; h < 8; ++h) {
        float e = cw2[h];
        A  = fmaf(e, cw1[3*h + 0], A);
        Bc = fmaf(e, cw1[3*h + 1], Bc);
        C  = fmaf(e, cw1[3*h + 2], C);
        D  = fmaf(e, cb1[h],       D);
    }
    D += cb2[0];
    const float rr = RATE_F / (float)bn[0];

    cp_wait<1>();                 // A (V, W1) complete; W2 may be in flight
    __syncthreads();

    // layer 1: x -> act1
    layer_body(Vs4, WsA, red, S1s, S2s, b1, g_act1, 1024, A, Bc, C, D, rr);
    grid_bar();

    // restage V <- act1 (L2-coherent via cp.async.cg); prefetch W3
    stage_tile(Vs4, (const float4*)g_act1);
    cp_commit();                                              // C
    if (blockIdx.x < 64)
        stage_tile(WsA, (const float4*)(W3 + (size_t)o_base * K_DIM));
    cp_commit();                                              // D (maybe empty)
    cp_wait<1>();                 // B, C complete; D may be in flight
    __syncthreads();

    // layer 2: act1 -> act2
    layer_body(Vs4, WsB, red, S1s, S2s, b2, g_act2, 1024, A, Bc, C, D, rr);
    grid_bar();

    if (blockIdx.x >= 64) return;  // layer 3 has only 512 rows

    stage_tile(Vs4, (const float4*)g_act2);
    cp_commit();                                              // E
    cp_wait<0>();                 // D, E complete
    __syncthreads();

    // layer 3: act2 -> out
    layer_body(Vs4, WsA, red, S1s, S2s, b3, outp, 512, A, Bc, C, D, rr);
}

extern "C" void kernel_launch(void* const* d_in, const int* in_sizes, int n_in,
                              void* d_out, int out_size)
{
    (void)in_sizes; (void)n_in; (void)out_size;
    const float* x   = (const float*)d_in[0];
    const float* W1  = (const float*)d_in[1];
    const float* b1  = (const float*)d_in[2];
    const float* W2  = (const float*)d_in[3];
    const float* b2  = (const float*)d_in[4];
    const float* W3  = (const float*)d_in[5];
    const float* b3  = (const float*)d_in[6];
    const float* cw1 = (const float*)d_in[7];
    const float* cb1 = (const float*)d_in[8];
    const float* cw2 = (const float*)d_in[9];
    const float* cb2 = (const float*)d_in[10];
    const int*   bn  = (const int*)d_in[11];
    float* outp = (float*)d_out;

    const int smem_bytes = (3 * 8 * VSTRIDE) * 16 + 1024 * 4 + 16 * 4;
    cudaFuncSetAttribute(hebbian_fused_kernel,
                         cudaFuncAttributeMaxDynamicSharedMemorySize, smem_bytes);

    hebbian_fused_kernel<<<NBLK, NTHR, smem_bytes>>>(
        x, W1, b1, W2, b2, W3, b3, cw1, cb1, cw2, cb2, bn, outp);
}

// round 5
// speedup vs baseline: 1.1364x; 1.1364x over previous
#include <cuda_runtime.h>
#include <cstdint>

// HebbianNet, fused persistent kernel. Closed form per layer:
//   z[b,o] = sum_i v[b,i]*W[o,i];  vj = relu(z + bias[o])
//   out    = vj + r*( A*S2[b] + Bc*z + (C*vj + D)*S1[b] )
// Shapes: B=8, K=1024 all layers, O = 1024,1024,512.
//
// 128 blocks x 256 threads, 8 output rows per block per layer.
// All weight tiles (W1,W2,W3 slices) prefetched to smem via cp.async at
// kernel entry. Grid barrier = atomic + tight __ldcv spin (no nanosleep).
// GEMV mapping: warp w -> K-quarter q=w>>1, half h=w&1;
//   lane slot = h*32+lane: row = slot>>3, batch = slot&7.
//   One scalar accumulator per lane; no shuffles; 4-way smem combine.

#define B_DIM   8
#define K_DIM   1024
#define RATE_F  0.001f
#define NBLK    128
#define NTHR    256
#define VSTRIDE 257            // float4 row stride (conflict-free padding)

__device__ __align__(16) float g_act1[B_DIM * K_DIM];
__device__ __align__(16) float g_act2[B_DIM * K_DIM];

__device__ unsigned g_count = 0;
__device__ unsigned g_gen   = 0;

__device__ __forceinline__ void grid_bar()
{
    __syncthreads();
    if (threadIdx.x == 0) {
        __threadfence();
        unsigned g = __ldcv(&g_gen);
        if (atomicAdd(&g_count, 1) == NBLK - 1) {
            atomicExch(&g_count, 0);
            __threadfence();
            atomicAdd(&g_gen, 1);
        } else {
            while (__ldcv(&g_gen) == g) { }   // tight spin, ~1 L2 RT per poll
        }
        __threadfence();
    }
    __syncthreads();
}

__device__ __forceinline__ void cp_async16(const float4* smem_dst, const float4* gsrc)
{
    uint32_t sa = (uint32_t)__cvta_generic_to_shared(smem_dst);
    asm volatile("cp.async.cg.shared.global [%0], [%1], 16;" :: "r"(sa), "l"(gsrc));
}
__device__ __forceinline__ void cp_commit() { asm volatile("cp.async.commit_group;"); }
template<int N> __device__ __forceinline__ void cp_wait()
{ asm volatile("cp.async.wait_group %0;" :: "n"(N)); }

// stage an 8x1024-float tile (2048 float4) into padded smem rows
__device__ __forceinline__ void stage_cp(float4* dst, const float4* src)
{
#pragma unroll
    for (int m = 0; m < 8; ++m) {
        int x = threadIdx.x + m * NTHR;
        cp_async16(&dst[(x >> 8) * VSTRIDE + (x & 255)], &src[x]);
    }
}

// restage activations from global (L2) into padded smem rows
__device__ __forceinline__ void stage_ldg(float4* dst, const float4* src)
{
#pragma unroll
    for (int m = 0; m < 8; ++m) {
        int x = threadIdx.x + m * NTHR;
        dst[(x >> 8) * VSTRIDE + (x & 255)] = __ldcg(&src[x]);
    }
}

__device__ __forceinline__ void layer_body(
    const float4* __restrict__ Vs, const float4* __restrict__ Ws,
    float* __restrict__ red, float* __restrict__ S1s, float* __restrict__ S2s,
    const float* __restrict__ bias, float* __restrict__ out, int O,
    float A, float Bc, float C, float D, float rr)
{
    const int tid  = threadIdx.x;
    const int wid  = tid >> 5;
    const int lane = tid & 31;

    // per-batch stats: warp w -> batch w
    {
        float s1 = 0.f, s2 = 0.f;
#pragma unroll
        for (int m = 0; m < 8; ++m) {
            float4 v = Vs[wid * VSTRIDE + m * 32 + lane];
            s1 += v.x + v.y + v.z + v.w;
            s2 = fmaf(v.x, v.x, s2); s2 = fmaf(v.y, v.y, s2);
            s2 = fmaf(v.z, v.z, s2); s2 = fmaf(v.w, v.w, s2);
        }
#pragma unroll
        for (int off = 16; off > 0; off >>= 1) {
            s1 += __shfl_xor_sync(0xffffffffu, s1, off);
            s2 += __shfl_xor_sync(0xffffffffu, s2, off);
        }
        if (lane == 0) { S1s[wid] = s1; S2s[wid] = s2; }
    }

    // GEMV: lane owns one (row,batch) over K-quarter q
    const int q    = wid >> 1;               // 0..3
    const int slot = (wid & 1) * 32 + lane;   // 0..63
    const int row  = slot >> 3;               // 0..7
    const int b    = slot & 7;

    const float4* vp = Vs + b   * VSTRIDE + q * 64;
    const float4* wp = Ws + row * VSTRIDE + q * 64;

    float acc = 0.f;
#pragma unroll
    for (int i = 0; i < 64; ++i) {
        float4 v = vp[i];
        float4 w = wp[i];
        acc = fmaf(w.x, v.x, acc);
        acc = fmaf(w.y, v.y, acc);
        acc = fmaf(w.z, v.z, acc);
        acc = fmaf(w.w, v.w, acc);
    }
    red[q * 64 + slot] = acc;
    __syncthreads();

    // combine K-quarters + epilogue (64 lanes: tid = row*8 + batch)
    if (tid < 64) {
        const int r  = tid >> 3;
        const int bb = tid & 7;
        const int o  = blockIdx.x * 8 + r;

        float z = red[tid] + red[64 + tid] + red[128 + tid] + red[192 + tid];
        float vj = fmaxf(z + bias[o], 0.f);
        float sh = fmaf(A, S2s[bb], fmaf(Bc, z, (C * vj + D) * S1s[bb]));
        out[(size_t)bb * O + o] = fmaf(rr, sh, vj);
    }
}

__global__ __launch_bounds__(NTHR, 1)
void hebbian_fused_kernel(const float* __restrict__ x,
                          const float* __restrict__ W1, const float* __restrict__ b1,
                          const float* __restrict__ W2, const float* __restrict__ b2,
                          const float* __restrict__ W3, const float* __restrict__ b3,
                          const float* __restrict__ cw1, const float* __restrict__ cb1,
                          const float* __restrict__ cw2, const float* __restrict__ cb2,
                          const int*   __restrict__ bn,
                          float*       __restrict__ outp)
{
    extern __shared__ float4 smem_dyn[];
    float4* Vs  = smem_dyn;                 // 8*257 f4
    float4* W1s = Vs  + 8 * VSTRIDE;
    float4* W2s = W1s + 8 * VSTRIDE;
    float4* W3s = W2s + 8 * VSTRIDE;
    float*  red = (float*)(W3s + 8 * VSTRIDE);   // 256 floats
    float*  S1s = red + 256;
    float*  S2s = S1s + 8;

    const int o_base = blockIdx.x * 8;

    // prefetch everything up front: {V,W1} | {W2} | {W3}
    stage_cp(Vs,  (const float4*)x);
    stage_cp(W1s, (const float4*)(W1 + (size_t)o_base * K_DIM));
    cp_commit();
    stage_cp(W2s, (const float4*)(W2 + (size_t)o_base * K_DIM));
    cp_commit();
    if (blockIdx.x < 64)
        stage_cp(W3s, (const float4*)(W3 + (size_t)o_base * K_DIM));
    cp_commit();

    // fold 1x1 convs into 4 scalars (overlaps async loads)
    float A = 0.f, Bc = 0.f, C = 0.f, D = 0.f;
#pragma unroll
    for (int h = 0; h < 8; ++h) {
        float e = cw2[h];
        A  = fmaf(e, cw1[3*h + 0], A);
        Bc = fmaf(e, cw1[3*h + 1], Bc);
        C  = fmaf(e, cw1[3*h + 2], C);
        D  = fmaf(e, cb1[h],       D);
    }
    D += cb2[0];
    const float rr = RATE_F / (float)bn[0];

    cp_wait<2>();                 // {V,W1} ready
    __syncthreads();
    layer_body(Vs, W1s, red, S1s, S2s, b1, g_act1, 1024, A, Bc, C, D, rr);

    grid_bar();
    stage_ldg(Vs, (const float4*)g_act1);
    cp_wait<1>();                 // {W2} ready (long since landed)
    __syncthreads();
    layer_body(Vs, W2s, red, S1s, S2s, b2, g_act2, 1024, A, Bc, C, D, rr);

    grid_bar();
    if (blockIdx.x >= 64) return; // layer 3 only needs 64 blocks

    stage_ldg(Vs, (const float4*)g_act2);
    cp_wait<0>();                 // {W3} ready
    __syncthreads();
    layer_body(Vs, W3s, red, S1s, S2s, b3, outp, 512, A, Bc, C, D, rr);
}

extern "C" void kernel_launch(void* const* d_in, const int* in_sizes, int n_in,
                              void* d_out, int out_size)
{
    (void)in_sizes; (void)n_in; (void)out_size;
    const float* x   = (const float*)d_in[0];
    const float* W1  = (const float*)d_in[1];
    const float* b1  = (const float*)d_in[2];
    const float* W2  = (const float*)d_in[3];
    const float* b2  = (const float*)d_in[4];
    const float* W3  = (const float*)d_in[5];
    const float* b3  = (const float*)d_in[6];
    const float* cw1 = (const float*)d_in[7];
    const float* cb1 = (const float*)d_in[8];
    const float* cw2 = (const float*)d_in[9];
    const float* cb2 = (const float*)d_in[10];
    const int*   bn  = (const int*)d_in[11];
    float* outp = (float*)d_out;

    const int smem_bytes = (4 * 8 * VSTRIDE) * 16 + 256 * 4 + 16 * 4;
    cudaFuncSetAttribute(hebbian_fused_kernel,
                         cudaFuncAttributeMaxDynamicSharedMemorySize, smem_bytes);

    hebbian_fused_kernel<<<NBLK, NTHR, smem_bytes>>>(
        x, W1, b1, W2, b2, W3, b3, cw1, cb1, cw2, cb2, bn, outp);
}